// round 3
// baseline (speedup 1.0000x reference)
#include <cuda_runtime.h>

// RelateBatch: one-hot block structure of batch_object_map (obj_q = n//8)
// collapses both einsum chains to per-8x8 diagonal-block row/col reductions.
// Reads 8.4 MB instead of 537 MB.
// Round 3: warp-per-tile, shuffle-only reductions (no smem/sync), MLP=4,
// streaming loads, 4096 warps for latency hiding.

#define EPSF 1e-12f

__device__ __forceinline__ float pnotf(float x, float a) {
    // a * log(max(1 - exp(min(x,0)), EPS)) + (1-a) * x
    float xm = fminf(x, 0.0f);
    float e  = __expf(xm);
    float l  = __logf(fmaxf(1.0f - e, EPSF));
    return fmaf(a, l, (1.0f - a) * x);
}

__global__ __launch_bounds__(256) void relate_batch_kernel(
    const float* __restrict__ log_prior,   // (64, 2, 512)
    const float* __restrict__ loglik,      // (64, 512, 512, 8)
    const float* __restrict__ quant,       // (64, 2)
    float* __restrict__ out)               // (64, 2, 512)
{
    constexpr int N = 512;
    const int p    = blockIdx.y;                          // 0..63
    const int g    = blockIdx.x * 8 + (threadIdx.x >> 5); // 0..63 (tile)
    const int lane = threadIdx.x & 31;
    const int i0   = lane >> 3;                           // 0..3
    const int j    = lane & 7;                            // 0..7
    const int r0   = i0;                                  // first row
    const int r1   = i0 + 4;                              // second row
    const int m    = g * 8 + j;                           // column object

    const float q0 = quant[2 * p + 0];
    const float q1 = quant[2 * p + 1];

    // Issue all 4 independent 128-bit streaming loads up front.
    const size_t b0 = (((size_t)p * N + g * 8 + r0) * N + m) * 8;
    const size_t b1 = (((size_t)p * N + g * 8 + r1) * N + m) * 8;
    float4 a0 = __ldcs(reinterpret_cast<const float4*>(loglik + b0));
    float4 a1 = __ldcs(reinterpret_cast<const float4*>(loglik + b0 + 4));
    float4 c0 = __ldcs(reinterpret_cast<const float4*>(loglik + b1));
    float4 c1 = __ldcs(reinterpret_cast<const float4*>(loglik + b1 + 4));

    const float lp0_r0 = log_prior[(p * 2 + 0) * N + g * 8 + r0];
    const float lp0_r1 = log_prior[(p * 2 + 0) * N + g * 8 + r1];
    const float lp1_m  = log_prior[(p * 2 + 1) * N + m];

    float llv0 = fminf((((a0.x + a0.y) + (a0.z + a0.w)) +
                        ((a1.x + a1.y) + (a1.z + a1.w))) * 0.125f, 0.0f);
    float llv1 = fminf((((c0.x + c0.y) + (c0.z + c0.w)) +
                        ((c1.x + c1.y) + (c1.z + c1.w))) * 0.125f, 0.0f);

    // Row path (out0): f(ll + lp1[m], q1), zero on diagonal.
    float v0 = (r0 == j) ? 0.0f : pnotf(llv0 + lp1_m, q1);
    float v1 = (r1 == j) ? 0.0f : pnotf(llv1 + lp1_m, q1);
    // Col path (out1): f(ll + lp0[n], q0), zero on diagonal.
    float w0 = (r0 == j) ? 0.0f : pnotf(llv0 + lp0_r0, q0);
    float w1 = (r1 == j) ? 0.0f : pnotf(llv1 + lp0_r1, q0);

    // Row sums: butterfly over the 8-lane j-groups.
    #pragma unroll
    for (int d = 1; d < 8; d <<= 1) {
        v0 += __shfl_xor_sync(0xffffffffu, v0, d);
        v1 += __shfl_xor_sync(0xffffffffu, v1, d);
    }
    // Col sums: local pair (rows i0 and i0+4), then butterfly across i-groups.
    float wc = w0 + w1;
    wc += __shfl_xor_sync(0xffffffffu, wc, 8);
    wc += __shfl_xor_sync(0xffffffffu, wc, 16);

    if (j == 0) {
        out[(p * 2 + 0) * N + g * 8 + r0] = pnotf(v0, q1) + lp0_r0;
        out[(p * 2 + 0) * N + g * 8 + r1] = pnotf(v1, q1) + lp0_r1;
    }
    if (i0 == 0) {
        out[(p * 2 + 1) * N + m] = pnotf(wc, q0) + lp1_m;
    }
}

extern "C" void kernel_launch(void* const* d_in, const int* in_sizes, int n_in,
                              void* d_out, int out_size) {
    const float* log_prior = (const float*)d_in[0];   // (64,2,512)
    const float* loglik    = (const float*)d_in[1];   // (64,512,512,8)
    const float* quant     = (const float*)d_in[2];   // (64,2)
    float* out = (float*)d_out;                       // (64,2,512)

    dim3 grid(8, 64);    // 8 warp-octets x 64 batches = 4096 warps
    dim3 block(256);
    relate_batch_kernel<<<grid, block>>>(log_prior, loglik, quant, out);
}

// round 4
// speedup vs baseline: 1.0435x; 1.0435x over previous
#include <cuda_runtime.h>

// RelateBatch: one-hot block structure of batch_object_map (obj_q = n//8)
// collapses both einsum chains to per-8x8 diagonal-block row/col reductions.
// Reads 8.4 MB instead of 537 MB.
// Round 4: warp-per-tile, shuffle-only reductions; 64-thread CTAs (2048
// blocks) to cut the per-SM drain-tail imbalance from 33% to 7%; 32-bit
// unsigned offset arithmetic.

#define EPSF 1e-12f

__device__ __forceinline__ float pnotf(float x, float a) {
    // a * log(max(1 - exp(min(x,0)), EPS)) + (1-a) * x
    float xm = fminf(x, 0.0f);
    float e  = __expf(xm);
    float l  = __logf(fmaxf(1.0f - e, EPSF));
    return fmaf(a, l, (1.0f - a) * x);
}

__global__ __launch_bounds__(64) void relate_batch_kernel(
    const float* __restrict__ log_prior,   // (64, 2, 512)
    const float* __restrict__ loglik,      // (64, 512, 512, 8)
    const float* __restrict__ quant,       // (64, 2)
    float* __restrict__ out)               // (64, 2, 512)
{
    constexpr unsigned N = 512;
    const unsigned p    = blockIdx.y;                          // 0..63
    const unsigned g    = blockIdx.x * 2u + (threadIdx.x >> 5); // 0..63 (tile)
    const unsigned lane = threadIdx.x & 31u;
    const unsigned i0   = lane >> 3;                           // 0..3
    const unsigned j    = lane & 7u;                           // 0..7
    const unsigned r0   = i0;                                  // first row
    const unsigned r1   = i0 + 4u;                             // second row
    const unsigned m    = g * 8u + j;                          // column object

    const float q0 = quant[2u * p + 0u];
    const float q1 = quant[2u * p + 1u];

    // 32-bit offsets: max index 64*512*512*8 = 134M elements (< 4G bytes).
    const unsigned b0 = (((p * N + g * 8u + r0) * N) + m) * 8u;
    const unsigned b1 = (((p * N + g * 8u + r1) * N) + m) * 8u;
    float4 a0 = __ldcs(reinterpret_cast<const float4*>(loglik + b0));
    float4 a1 = __ldcs(reinterpret_cast<const float4*>(loglik + b0 + 4u));
    float4 c0 = __ldcs(reinterpret_cast<const float4*>(loglik + b1));
    float4 c1 = __ldcs(reinterpret_cast<const float4*>(loglik + b1 + 4u));

    const float lp0_r0 = log_prior[(p * 2u + 0u) * N + g * 8u + r0];
    const float lp0_r1 = log_prior[(p * 2u + 0u) * N + g * 8u + r1];
    const float lp1_m  = log_prior[(p * 2u + 1u) * N + m];

    float llv0 = fminf((((a0.x + a0.y) + (a0.z + a0.w)) +
                        ((a1.x + a1.y) + (a1.z + a1.w))) * 0.125f, 0.0f);
    float llv1 = fminf((((c0.x + c0.y) + (c0.z + c0.w)) +
                        ((c1.x + c1.y) + (c1.z + c1.w))) * 0.125f, 0.0f);

    // Diagonal masks as float multipliers (avoid divergent selects).
    const float d0 = (r0 == j) ? 0.0f : 1.0f;
    const float d1 = (r1 == j) ? 0.0f : 1.0f;

    // Row path (out0): f(ll + lp1[m], q1); col path (out1): f(ll + lp0[n], q0).
    float v0 = d0 * pnotf(llv0 + lp1_m, q1);
    float v1 = d1 * pnotf(llv1 + lp1_m, q1);
    float w0 = d0 * pnotf(llv0 + lp0_r0, q0);
    float w1 = d1 * pnotf(llv1 + lp0_r1, q0);

    // Row sums: butterfly over the 8-lane j-groups (two rows in parallel).
    #pragma unroll
    for (int d = 1; d < 8; d <<= 1) {
        v0 += __shfl_xor_sync(0xffffffffu, v0, d);
        v1 += __shfl_xor_sync(0xffffffffu, v1, d);
    }
    // Col sums: local pair (rows i0 and i0+4), then butterfly across i-groups.
    float wc = w0 + w1;
    wc += __shfl_xor_sync(0xffffffffu, wc, 8);
    wc += __shfl_xor_sync(0xffffffffu, wc, 16);

    if (j == 0u) {
        out[(p * 2u + 0u) * N + g * 8u + r0] = pnotf(v0, q1) + lp0_r0;
        out[(p * 2u + 0u) * N + g * 8u + r1] = pnotf(v1, q1) + lp0_r1;
    }
    if (i0 == 0u) {
        out[(p * 2u + 1u) * N + m] = pnotf(wc, q0) + lp1_m;
    }
}

extern "C" void kernel_launch(void* const* d_in, const int* in_sizes, int n_in,
                              void* d_out, int out_size) {
    const float* log_prior = (const float*)d_in[0];   // (64,2,512)
    const float* loglik    = (const float*)d_in[1];   // (64,512,512,8)
    const float* quant     = (const float*)d_in[2];   // (64,2)
    float* out = (float*)d_out;                       // (64,2,512)

    dim3 grid(32, 64);   // 32 tile-pairs x 64 batches = 2048 blocks (2 warps ea)
    dim3 block(64);
    relate_batch_kernel<<<grid, block>>>(log_prior, loglik, quant, out);
}